// round 8
// baseline (speedup 1.0000x reference)
#include <cuda_runtime.h>
#include <cuda_bf16.h>
#include <cstdint>

#define B_   2
#define S_   2048
#define E_   1024
#define H_   16
#define D_   64
#define BH_  (B_*H_)      // 32
#define TOK_ (B_*S_)      // 4096
#define SLAB 256          // q-rows per slab (16 slabs total)

// single dynamic-smem symbol shared by all kernels
extern __shared__ __align__(16) char dynsm[];

// ===========================================================================
// helpers
// ===========================================================================
__device__ __forceinline__ uint32_t smem_u32(const void* p) {
    uint32_t a;
    asm("{ .reg .u64 t; cvta.to.shared.u64 t, %1; cvt.u32.u64 %0, t; }" : "=r"(a) : "l"(p));
    return a;
}
#define CP_COMMIT()  asm volatile("cp.async.commit_group;" ::: "memory")
#define CP_WAIT0()   asm volatile("cp.async.wait_group 0;" ::: "memory")
#define CP_WAIT1()   asm volatile("cp.async.wait_group 1;" ::: "memory")

__device__ __forceinline__ void cp16(uint32_t dst, const void* src) {
    asm volatile("cp.async.cg.shared.global [%0], [%1], 16;" :: "r"(dst), "l"(src) : "memory");
}

// m16n8k16 bf16 MMA, fp32 accum. A row-major, B col-major ([n][k] row-major).
__device__ __forceinline__ void mma_bf16(float c[4], const uint32_t a[4], const uint32_t b[2]) {
    asm volatile("mma.sync.aligned.m16n8k16.row.col.f32.bf16.bf16.f32 "
        "{%0,%1,%2,%3}, {%4,%5,%6,%7}, {%8,%9}, {%0,%1,%2,%3};"
        : "+f"(c[0]), "+f"(c[1]), "+f"(c[2]), "+f"(c[3])
        : "r"(a[0]), "r"(a[1]), "r"(a[2]), "r"(a[3]), "r"(b[0]), "r"(b[1]));
}

__device__ __forceinline__ void split2(float v, __nv_bfloat16& h, __nv_bfloat16& l) {
    h = __float2bfloat16(v);
    l = __float2bfloat16(v - __bfloat162float(h));
}

// A-fragment from a row-major smem tile (stride bytes), rows r0/r0+8, k-bytes kb
__device__ __forceinline__ void lda4(uint32_t a[4], const char* t, int stride, int r0, int kb) {
    a[0] = *(const uint32_t*)(t + (size_t)(r0    )*stride + kb);
    a[1] = *(const uint32_t*)(t + (size_t)(r0 + 8)*stride + kb);
    a[2] = *(const uint32_t*)(t + (size_t)(r0    )*stride + kb + 16);
    a[3] = *(const uint32_t*)(t + (size_t)(r0 + 8)*stride + kb + 16);
}
// B-fragment from [n][k] row-major tile
__device__ __forceinline__ void ldb2(uint32_t b[2], const char* t, int stride, int n, int kb) {
    b[0] = *(const uint32_t*)(t + (size_t)n*stride + kb);
    b[1] = *(const uint32_t*)(t + (size_t)n*stride + kb + 16);
}

// load [rows x 32] bf16 chunk -> smem rows of 80 bytes (32 bf16 + 8 pad)
__device__ __forceinline__ void ld_chunk32(char* s, const __nv_bfloat16* g, int ld, int rows) {
    uint32_t sb = smem_u32(s);
    for (int i = threadIdx.x; i < rows*4; i += 256) {
        int r = i >> 2, c = i & 3;
        cp16(sb + r*80 + c*16, g + (size_t)r*ld + c*8);
    }
}
// load [rows x 64] bf16 chunk -> smem rows of 144 bytes (64 bf16 + 8 pad)
__device__ __forceinline__ void ld_chunk64(char* s, const __nv_bfloat16* g, int ld, int rows) {
    uint32_t sb = smem_u32(s);
    for (int i = threadIdx.x; i < rows*8; i += 256) {
        int r = i >> 3, c = i & 7;
        cp16(sb + r*144 + c*16, g + (size_t)r*ld + c*8);
    }
}

// ===========================================================================
// static device scratch (slab buffers are reused across all 16 slabs -> L2-hot)
// ===========================================================================
__device__ float          d_scores_s[H_*(size_t)SLAB*S_];  // 33.5 MB slab scores
__device__ __nv_bfloat16  d_Phs[H_*(size_t)SLAB*S_];       // 16.8 MB slab P hi
__device__ __nv_bfloat16  d_Pls[H_*(size_t)SLAB*S_];       // 16.8 MB slab P lo
__device__ __nv_bfloat16  d_Xh[TOK_*E_], d_Xl[TOK_*E_];
__device__ __nv_bfloat16  d_Wth[E_*E_],  d_Wtl[E_*E_];     // W^T split (reused)
__device__ __nv_bfloat16  d_Qh[BH_*S_*D_], d_Ql[BH_*S_*D_];
__device__ __nv_bfloat16  d_Kh[BH_*S_*D_], d_Kl[BH_*S_*D_];
__device__ __nv_bfloat16  d_Vh[BH_*S_*D_], d_Vl[BH_*S_*D_];
__device__ __nv_bfloat16  d_Ch[TOK_*E_],  d_Cl[TOK_*E_];   // ctx split [B,S,E]
__device__ float          d_mixsm[H_*H_];

// ===========================================================================
// 0) softmax of the 16x16 head-mixing matrix
// ===========================================================================
__global__ void mix_softmax_kernel(const float* __restrict__ hm) {
    int g = threadIdx.x;
    if (g >= H_) return;
    float m = -1e30f;
    #pragma unroll
    for (int h = 0; h < H_; h++) m = fmaxf(m, hm[g*H_ + h]);
    float e[H_]; float s = 0.f;
    #pragma unroll
    for (int h = 0; h < H_; h++) { e[h] = expf(hm[g*H_ + h] - m); s += e[h]; }
    float inv = 1.f / s;
    #pragma unroll
    for (int h = 0; h < H_; h++) d_mixsm[g*H_ + h] = e[h] * inv;
}

// ===========================================================================
// 1) fp32 -> split-bf16 (flat, vectorized)
// ===========================================================================
__global__ __launch_bounds__(256) void split_f32(const float* __restrict__ in,
        __nv_bfloat16* __restrict__ oh, __nv_bfloat16* __restrict__ ol, int n4) {
    int i = blockIdx.x*256 + threadIdx.x;
    if (i >= n4) return;
    float4 v = ((const float4*)in)[i];
    __nv_bfloat16 h0,h1,h2,h3,l0,l1,l2,l3;
    split2(v.x,h0,l0); split2(v.y,h1,l1); split2(v.z,h2,l2); split2(v.w,h3,l3);
    __nv_bfloat162 p;
    p.x=h0; p.y=h1; ((__nv_bfloat162*)oh)[2*i]   = p;
    p.x=h2; p.y=h3; ((__nv_bfloat162*)oh)[2*i+1] = p;
    p.x=l0; p.y=l1; ((__nv_bfloat162*)ol)[2*i]   = p;
    p.x=l2; p.y=l3; ((__nv_bfloat162*)ol)[2*i+1] = p;
}

// ===========================================================================
// 2) W [K,N] fp32 -> W^T [N,K] split-bf16
// ===========================================================================
__global__ void split_wt(const float* __restrict__ W,
        __nv_bfloat16* __restrict__ oh, __nv_bfloat16* __restrict__ ol) {
    __shared__ float t[32][33];
    int n0 = blockIdx.x*32, k0 = blockIdx.y*32;
    int tx = threadIdx.x, ty = threadIdx.y;
    #pragma unroll
    for (int i = 0; i < 4; i++)
        t[ty+8*i][tx] = W[(size_t)(k0+ty+8*i)*E_ + n0+tx];
    __syncthreads();
    #pragma unroll
    for (int i = 0; i < 4; i++) {
        float v = t[tx][ty+8*i];
        size_t idx = (size_t)(n0+ty+8*i)*E_ + k0 + tx;
        __nv_bfloat16 hb, lb; split2(v, hb, lb);
        oh[idx] = hb; ol[idx] = lb;
    }
}

// ===========================================================================
// 3) projection GEMM: C[4096,1024] = A @ B^T. 128x128 block, 8 warps @ 32x64.
//    mode 0: fp32 + bias (final output).  mode 1: split-bf16 [B,H,S,D].
// ===========================================================================
#define PROJ_SMEM (2*4*10240)   // 81920
__global__ __launch_bounds__(256) void gemm_mma(
    const __nv_bfloat16* __restrict__ Ah_, const __nv_bfloat16* __restrict__ Al_,
    const __nv_bfloat16* __restrict__ Bh_, const __nv_bfloat16* __restrict__ Bl_,
    const float* __restrict__ bias, int mode,
    float* __restrict__ outF, __nv_bfloat16* __restrict__ outH, __nv_bfloat16* __restrict__ outL)
{
    char* sm = dynsm;
    const int tid = threadIdx.x, lane = tid & 31, wid = tid >> 5;
    const int wm = wid >> 1, wn = wid & 1;
    const int g = lane >> 2, tg = lane & 3;
    const int bm = blockIdx.y*128, bn = blockIdx.x*128;

    float acc[2][8][4];
    #pragma unroll
    for (int i = 0; i < 2; i++)
        #pragma unroll
        for (int j = 0; j < 8; j++)
            #pragma unroll
            for (int q = 0; q < 4; q++) acc[i][j][q] = 0.f;

    const __nv_bfloat16* gT[4] = { Ah_ + (size_t)bm*E_, Al_ + (size_t)bm*E_,
                                   Bh_ + (size_t)bn*E_, Bl_ + (size_t)bn*E_ };
    #pragma unroll
    for (int t = 0; t < 4; t++) ld_chunk32(sm + t*10240, gT[t], E_, 128);
    CP_COMMIT();

    for (int c = 0; c < 32; c++) {
        if (c < 31) {
            int k0 = (c+1)*32;
            char* st = sm + ((c+1)&1)*40960;
            #pragma unroll
            for (int t = 0; t < 4; t++) ld_chunk32(st + t*10240, gT[t] + k0, E_, 128);
            CP_COMMIT(); CP_WAIT1();
        } else CP_WAIT0();
        __syncthreads();
        const char* st = sm + (c&1)*40960;
        #pragma unroll
        for (int ks = 0; ks < 2; ks++) {
            int kb = ks*32 + tg*4;
            uint32_t aH[2][4], aL[2][4], bH[8][2], bL[8][2];
            #pragma unroll
            for (int i = 0; i < 2; i++) {
                int r0 = wm*32 + i*16 + g;
                lda4(aH[i], st,          80, r0, kb);
                lda4(aL[i], st + 10240,  80, r0, kb);
            }
            #pragma unroll
            for (int j = 0; j < 8; j++) {
                int n = wn*64 + j*8 + g;
                ldb2(bH[j], st + 20480, 80, n, kb);
                ldb2(bL[j], st + 30720, 80, n, kb);
            }
            #pragma unroll
            for (int i = 0; i < 2; i++)
                #pragma unroll
                for (int j = 0; j < 8; j++) {
                    mma_bf16(acc[i][j], aH[i], bH[j]);
                    mma_bf16(acc[i][j], aH[i], bL[j]);
                    mma_bf16(acc[i][j], aL[i], bH[j]);
                }
        }
        __syncthreads();
    }

    #pragma unroll
    for (int j = 0; j < 8; j++) {
        int c = bn + wn*64 + j*8 + tg*2;
        float b0 = bias[c], b1 = bias[c+1];
        #pragma unroll
        for (int i = 0; i < 2; i++) {
            #pragma unroll
            for (int half = 0; half < 2; half++) {
                int r = bm + wm*32 + i*16 + g + half*8;
                float v0 = acc[i][j][half*2+0] + b0;
                float v1 = acc[i][j][half*2+1] + b1;
                if (mode == 0) {
                    float2 f; f.x = v0; f.y = v1;
                    *(float2*)&outF[(size_t)r*E_ + c] = f;
                } else {
                    int bb = r >> 11, s = r & (S_-1);
                    int h = c >> 6,  d = c & 63;
                    __nv_bfloat16 h0,l0,h1,l1;
                    split2(v0,h0,l0); split2(v1,h1,l1);
                    size_t idx = (((size_t)bb*H_ + h)*S_ + s)*D_ + d;
                    __nv_bfloat162 ph; ph.x=h0; ph.y=h1;
                    __nv_bfloat162 pl; pl.x=l0; pl.y=l1;
                    *(__nv_bfloat162*)&outH[idx] = ph;
                    *(__nv_bfloat162*)&outL[idx] = pl;
                }
            }
        }
    }
}

// ===========================================================================
// 4) scores slab: s = Q K^T / 8 for q in [q0, q0+SLAB), one (b) at a time.
//    grid (S_/128, SLAB/128, H_). Writes slab buffer (L2-hot).
// ===========================================================================
#define SC_SMEM (4*18432)   // 73728
__global__ __launch_bounds__(256) void scores_mma(int b, int q0)
{
    char* sm = dynsm;
    const int tid = threadIdx.x, lane = tid & 31, wid = tid >> 5;
    const int wm = wid >> 1, wn = wid & 1;
    const int g = lane >> 2, tg = lane & 3;
    const int h = blockIdx.z;
    const int bh = b*H_ + h;
    const int bmL = blockIdx.y*128;          // q local to slab
    const int bmG = q0 + bmL;                // q global
    const int bn  = blockIdx.x*128;

    ld_chunk64(sm,           d_Qh + (size_t)bh*S_*D_ + (size_t)bmG*D_, D_, 128);
    ld_chunk64(sm + 18432,   d_Ql + (size_t)bh*S_*D_ + (size_t)bmG*D_, D_, 128);
    ld_chunk64(sm + 36864,   d_Kh + (size_t)bh*S_*D_ + (size_t)bn*D_,  D_, 128);
    ld_chunk64(sm + 55296,   d_Kl + (size_t)bh*S_*D_ + (size_t)bn*D_,  D_, 128);
    CP_COMMIT(); CP_WAIT0();
    __syncthreads();

    float acc[2][8][4];
    #pragma unroll
    for (int i = 0; i < 2; i++)
        #pragma unroll
        for (int j = 0; j < 8; j++)
            #pragma unroll
            for (int q = 0; q < 4; q++) acc[i][j][q] = 0.f;

    #pragma unroll
    for (int ks = 0; ks < 4; ks++) {
        int kb = ks*32 + tg*4;
        uint32_t aH[2][4], aL[2][4], bH[8][2], bL[8][2];
        #pragma unroll
        for (int i = 0; i < 2; i++) {
            int r0 = wm*32 + i*16 + g;
            lda4(aH[i], sm,         144, r0, kb);
            lda4(aL[i], sm + 18432, 144, r0, kb);
        }
        #pragma unroll
        for (int j = 0; j < 8; j++) {
            int n = wn*64 + j*8 + g;
            ldb2(bH[j], sm + 36864, 144, n, kb);
            ldb2(bL[j], sm + 55296, 144, n, kb);
        }
        #pragma unroll
        for (int i = 0; i < 2; i++)
            #pragma unroll
            for (int j = 0; j < 8; j++) {
                mma_bf16(acc[i][j], aH[i], bH[j]);
                mma_bf16(acc[i][j], aH[i], bL[j]);
                mma_bf16(acc[i][j], aL[i], bH[j]);
            }
    }

    float* outb = d_scores_s + (size_t)h*SLAB*S_;
    #pragma unroll
    for (int i = 0; i < 2; i++)
        #pragma unroll
        for (int j = 0; j < 8; j++) {
            int c = bn + wn*64 + j*8 + tg*2;
            #pragma unroll
            for (int half = 0; half < 2; half++) {
                int r = bmL + wm*32 + i*16 + g + half*8;
                float2 f;
                f.x = acc[i][j][half*2+0] * 0.125f;
                f.y = acc[i][j][half*2+1] * 0.125f;
                *(float2*)&outb[(size_t)r*S_ + c] = f;
            }
        }
}

// ===========================================================================
// 5) fused row-softmax + head mixing on one slab row (q_loc = blockIdx.x).
//    Reads slab scores, writes slab split-bf16 P. All L2-hot.
// ===========================================================================
#define SMX_SMEM ((H_*S_ + 16 + 256)*4)   // 132160
__global__ __launch_bounds__(256) void softmax_mix_kernel()
{
    float* sm   = (float*)dynsm;
    float* inv  = sm + H_*S_;
    float* mixs = inv + 16;
    const int q_loc = blockIdx.x;
    const int tid = threadIdx.x;

    for (int i = tid; i < H_*S_/4; i += 256) {
        int h = i >> 9, k4 = i & 511;
        ((float4*)sm)[i] = *(const float4*)(d_scores_s + (size_t)h*SLAB*S_
                                            + (size_t)q_loc*S_ + k4*4);
    }
    mixs[tid] = d_mixsm[tid & 255];
    __syncthreads();

    int w = tid >> 5, lane = tid & 31;
    #pragma unroll
    for (int hh = 0; hh < 2; hh++) {
        int h = w*2 + hh;
        float* row = sm + h*S_;
        float m = -1e30f;
        for (int j = lane; j < S_; j += 32) m = fmaxf(m, row[j]);
        #pragma unroll
        for (int o = 16; o; o >>= 1) m = fmaxf(m, __shfl_xor_sync(0xFFFFFFFFu, m, o));
        float s = 0.f;
        for (int j = lane; j < S_; j += 32) { float e = __expf(row[j] - m); row[j] = e; s += e; }
        #pragma unroll
        for (int o = 16; o; o >>= 1) s += __shfl_xor_sync(0xFFFFFFFFu, s, o);
        if (lane == 0) inv[h] = 1.f / s;
    }
    __syncthreads();

    for (int k = tid; k < S_; k += 256) {
        float a[H_];
        #pragma unroll
        for (int h = 0; h < H_; h++) a[h] = sm[h*S_ + k] * inv[h];
        #pragma unroll
        for (int g = 0; g < H_; g++) {
            float o = 0.f;
            #pragma unroll
            for (int h = 0; h < H_; h++) o = fmaf(mixs[g*16 + h], a[h], o);
            __nv_bfloat16 hb, lb; split2(o, hb, lb);
            size_t idx = (size_t)g*SLAB*S_ + (size_t)q_loc*S_ + k;
            d_Phs[idx] = hb; d_Pls[idx] = lb;
        }
    }
}

// ===========================================================================
// 6) ctx slab: ctx = P @ V. grid (SLAB/32, H_). 32x64 block tile, 8 warps
//    each owning an 8-wide d-slice. K=2048, double-buffered 32-k chunks.
// ===========================================================================
#define CTX_STAGE (2*2560 + 2*4608)       // 14336
#define CTX_SMEM  (2*CTX_STAGE)           // 28672
__global__ __launch_bounds__(256) void ctx_mma(int b, int q0)
{
    char* sm = dynsm;
    const int tid = threadIdx.x, lane = tid & 31, wid = tid >> 5;
    const int wn = wid;                    // 0..7 -> d slice [wn*8, wn*8+8)
    const int g = lane >> 2, tg = lane & 3;
    const int ghead = blockIdx.y;
    const int bg = b*H_ + ghead;
    const int qt = blockIdx.x*32;          // q local to slab

    const __nv_bfloat16* ph = d_Phs + (size_t)ghead*SLAB*S_ + (size_t)qt*S_;
    const __nv_bfloat16* pl = d_Pls + (size_t)ghead*SLAB*S_ + (size_t)qt*S_;
    const __nv_bfloat16* vh = d_Vh + (size_t)bg*S_*D_;
    const __nv_bfloat16* vl = d_Vl + (size_t)bg*S_*D_;

    float acc[2][4];
    #pragma unroll
    for (int i = 0; i < 2; i++)
        #pragma unroll
        for (int q = 0; q < 4; q++) acc[i][q] = 0.f;

    {   // preload chunk 0
        char* st = sm;
        ld_chunk32(st,        ph, S_, 32);
        ld_chunk32(st + 2560, pl, S_, 32);
        ld_chunk64(st + 5120, vh, D_, 32);
        ld_chunk64(st + 9728, vl, D_, 32);
        CP_COMMIT();
    }
    for (int c = 0; c < 64; c++) {
        if (c < 63) {
            int k0 = (c+1)*32;
            char* st = sm + ((c+1)&1)*CTX_STAGE;
            ld_chunk32(st,        ph + k0, S_, 32);
            ld_chunk32(st + 2560, pl + k0, S_, 32);
            ld_chunk64(st + 5120, vh + (size_t)k0*D_, D_, 32);
            ld_chunk64(st + 9728, vl + (size_t)k0*D_, D_, 32);
            CP_COMMIT(); CP_WAIT1();
        } else CP_WAIT0();
        __syncthreads();
        const char* st = sm + (c&1)*CTX_STAGE;
        const char* vH = st + 5120;
        const char* vL = st + 9728;
        #pragma unroll
        for (int ks = 0; ks < 2; ks++) {
            int kb = ks*32 + tg*4;
            uint32_t aH[2][4], aL[2][4], bH[2], bL[2];
            #pragma unroll
            for (int i = 0; i < 2; i++) {
                int r0 = i*16 + g;
                lda4(aH[i], st,        80, r0, kb);
                lda4(aL[i], st + 2560, 80, r0, kb);
            }
            int krow = ks*16 + tg*2;
            int n2 = (wn*8 + g)*2;
            {
                uint32_t x0, x1, x2, x3;
                x0 = *(const unsigned short*)(vH + (krow  )*144 + n2);
                x1 = *(const unsigned short*)(vH + (krow+1)*144 + n2);
                x2 = *(const unsigned short*)(vH + (krow+8)*144 + n2);
                x3 = *(const unsigned short*)(vH + (krow+9)*144 + n2);
                bH[0] = x0 | (x1 << 16);
                bH[1] = x2 | (x3 << 16);
                x0 = *(const unsigned short*)(vL + (krow  )*144 + n2);
                x1 = *(const unsigned short*)(vL + (krow+1)*144 + n2);
                x2 = *(const unsigned short*)(vL + (krow+8)*144 + n2);
                x3 = *(const unsigned short*)(vL + (krow+9)*144 + n2);
                bL[0] = x0 | (x1 << 16);
                bL[1] = x2 | (x3 << 16);
            }
            #pragma unroll
            for (int i = 0; i < 2; i++) {
                mma_bf16(acc[i], aH[i], bH);
                mma_bf16(acc[i], aH[i], bL);
                mma_bf16(acc[i], aL[i], bH);
            }
        }
        __syncthreads();
    }

    #pragma unroll
    for (int i = 0; i < 2; i++) {
        int d = wn*8 + tg*2;
        #pragma unroll
        for (int half = 0; half < 2; half++) {
            int q = q0 + qt + i*16 + g + half*8;
            float v0 = acc[i][half*2+0];
            float v1 = acc[i][half*2+1];
            __nv_bfloat16 h0,l0,h1,l1;
            split2(v0,h0,l0); split2(v1,h1,l1);
            size_t idx = ((size_t)b*S_ + q)*E_ + ghead*D_ + d;
            __nv_bfloat162 ph2; ph2.x=h0; ph2.y=h1;
            __nv_bfloat162 pl2; pl2.x=l0; pl2.y=l1;
            *(__nv_bfloat162*)&d_Ch[idx] = ph2;
            *(__nv_bfloat162*)&d_Cl[idx] = pl2;
        }
    }
}

// ===========================================================================
// kernel_launch
// ===========================================================================
extern "C" void kernel_launch(void* const* d_in, const int* in_sizes, int n_in,
                              void* d_out, int out_size)
{
    (void)in_sizes; (void)n_in; (void)out_size;
    const float* query = (const float*)d_in[0];
    const float* key_  = (const float*)d_in[1];
    const float* value = (const float*)d_in[2];
    const float* Wq = (const float*)d_in[3];
    const float* bq = (const float*)d_in[4];
    const float* Wk = (const float*)d_in[5];
    const float* bk = (const float*)d_in[6];
    const float* Wv = (const float*)d_in[7];
    const float* bv = (const float*)d_in[8];
    const float* hm = (const float*)d_in[9];
    const float* Wo = (const float*)d_in[10];
    const float* bo = (const float*)d_in[11];
    float* out = (float*)d_out;

    cudaFuncSetAttribute(gemm_mma,           cudaFuncAttributeMaxDynamicSharedMemorySize, PROJ_SMEM);
    cudaFuncSetAttribute(scores_mma,         cudaFuncAttributeMaxDynamicSharedMemorySize, SC_SMEM);
    cudaFuncSetAttribute(softmax_mix_kernel, cudaFuncAttributeMaxDynamicSharedMemorySize, SMX_SMEM);
    cudaFuncSetAttribute(ctx_mma,            cudaFuncAttributeMaxDynamicSharedMemorySize, CTX_SMEM);

    __nv_bfloat16 *Xh, *Xl, *Wth, *Wtl, *Qh, *Ql, *Kh, *Kl, *Vh, *Vl, *Ch, *Cl;
    cudaGetSymbolAddress((void**)&Xh,  d_Xh);  cudaGetSymbolAddress((void**)&Xl,  d_Xl);
    cudaGetSymbolAddress((void**)&Wth, d_Wth); cudaGetSymbolAddress((void**)&Wtl, d_Wtl);
    cudaGetSymbolAddress((void**)&Qh,  d_Qh);  cudaGetSymbolAddress((void**)&Ql,  d_Ql);
    cudaGetSymbolAddress((void**)&Kh,  d_Kh);  cudaGetSymbolAddress((void**)&Kl,  d_Kl);
    cudaGetSymbolAddress((void**)&Vh,  d_Vh);  cudaGetSymbolAddress((void**)&Vl,  d_Vl);
    cudaGetSymbolAddress((void**)&Ch,  d_Ch);  cudaGetSymbolAddress((void**)&Cl,  d_Cl);

    const int n4 = TOK_*E_/4;
    dim3 wt(32, 32), wtb(32, 8);
    dim3 gp(E_/128, TOK_/128);   // (8, 32)

    mix_softmax_kernel<<<1, 16>>>(hm);

    // Q projection
    split_wt<<<wt, wtb>>>(Wq, Wth, Wtl);
    split_f32<<<n4/256, 256>>>(query, Xh, Xl, n4);
    gemm_mma<<<gp, 256, PROJ_SMEM>>>(Xh, Xl, Wth, Wtl, bq, 1, nullptr, Qh, Ql);
    // K projection
    split_wt<<<wt, wtb>>>(Wk, Wth, Wtl);
    split_f32<<<n4/256, 256>>>(key_, Xh, Xl, n4);
    gemm_mma<<<gp, 256, PROJ_SMEM>>>(Xh, Xl, Wth, Wtl, bk, 1, nullptr, Kh, Kl);
    // V projection
    split_wt<<<wt, wtb>>>(Wv, Wth, Wtl);
    split_f32<<<n4/256, 256>>>(value, Xh, Xl, n4);
    gemm_mma<<<gp, 256, PROJ_SMEM>>>(Xh, Xl, Wth, Wtl, bv, 1, nullptr, Vh, Vl);

    // attention middle, slab by slab (intermediates stay in L2)
    for (int b = 0; b < B_; b++) {
        for (int s = 0; s < S_/SLAB; s++) {
            int q0 = s * SLAB;
            scores_mma<<<dim3(S_/128, SLAB/128, H_), 256, SC_SMEM>>>(b, q0);
            softmax_mix_kernel<<<SLAB, 256, SMX_SMEM>>>();
            ctx_mma<<<dim3(SLAB/32, H_), 256, CTX_SMEM>>>(b, q0);
        }
    }

    // output projection
    split_wt<<<wt, wtb>>>(Wo, Wth, Wtl);
    gemm_mma<<<gp, 256, PROJ_SMEM>>>(Ch, Cl, Wth, Wtl, bo, 0, out, nullptr, nullptr);
}

// round 9
// speedup vs baseline: 1.4397x; 1.4397x over previous
#include <cuda_runtime.h>
#include <cuda_bf16.h>
#include <cstdint>

#define B_   2
#define S_   2048
#define E_   1024
#define H_   16
#define D_   64
#define BH_  (B_*H_)      // 32
#define TOK_ (B_*S_)      // 4096

// single dynamic-smem symbol shared by all kernels
extern __shared__ __align__(16) char dynsm[];

// ===========================================================================
// helpers
// ===========================================================================
__device__ __forceinline__ uint32_t smem_u32(const void* p) {
    uint32_t a;
    asm("{ .reg .u64 t; cvta.to.shared.u64 t, %1; cvt.u32.u64 %0, t; }" : "=r"(a) : "l"(p));
    return a;
}
#define CP_COMMIT()  asm volatile("cp.async.commit_group;" ::: "memory")
#define CP_WAIT0()   asm volatile("cp.async.wait_group 0;" ::: "memory")
#define CP_WAIT1()   asm volatile("cp.async.wait_group 1;" ::: "memory")

__device__ __forceinline__ void cp16(uint32_t dst, const void* src) {
    asm volatile("cp.async.cg.shared.global [%0], [%1], 16;" :: "r"(dst), "l"(src) : "memory");
}

// m16n8k16 bf16 MMA, fp32 accum. A row-major, B col-major ([n][k] row-major).
__device__ __forceinline__ void mma_bf16(float c[4], const uint32_t a[4], const uint32_t b[2]) {
    asm volatile("mma.sync.aligned.m16n8k16.row.col.f32.bf16.bf16.f32 "
        "{%0,%1,%2,%3}, {%4,%5,%6,%7}, {%8,%9}, {%0,%1,%2,%3};"
        : "+f"(c[0]), "+f"(c[1]), "+f"(c[2]), "+f"(c[3])
        : "r"(a[0]), "r"(a[1]), "r"(a[2]), "r"(a[3]), "r"(b[0]), "r"(b[1]));
}

__device__ __forceinline__ void split2(float v, __nv_bfloat16& h, __nv_bfloat16& l) {
    h = __float2bfloat16(v);
    l = __float2bfloat16(v - __bfloat162float(h));
}

// A-fragment from a row-major smem tile (stride bytes), rows r0/r0+8, k-bytes kb
__device__ __forceinline__ void lda4(uint32_t a[4], const char* t, int stride, int r0, int kb) {
    a[0] = *(const uint32_t*)(t + (size_t)(r0    )*stride + kb);
    a[1] = *(const uint32_t*)(t + (size_t)(r0 + 8)*stride + kb);
    a[2] = *(const uint32_t*)(t + (size_t)(r0    )*stride + kb + 16);
    a[3] = *(const uint32_t*)(t + (size_t)(r0 + 8)*stride + kb + 16);
}
// B-fragment from [n][k] row-major tile
__device__ __forceinline__ void ldb2(uint32_t b[2], const char* t, int stride, int n, int kb) {
    b[0] = *(const uint32_t*)(t + (size_t)n*stride + kb);
    b[1] = *(const uint32_t*)(t + (size_t)n*stride + kb + 16);
}

// load [rows x 32] bf16 chunk -> smem rows of 80 bytes (32 bf16 + 8 pad)
__device__ __forceinline__ void ld_chunk32(char* s, const __nv_bfloat16* g, int ld, int rows) {
    uint32_t sb = smem_u32(s);
    for (int i = threadIdx.x; i < rows*4; i += 256) {
        int r = i >> 2, c = i & 3;
        cp16(sb + r*80 + c*16, g + (size_t)r*ld + c*8);
    }
}
// load [rows x 64] bf16 chunk -> smem rows of 144 bytes (64 bf16 + 8 pad)
__device__ __forceinline__ void ld_chunk64(char* s, const __nv_bfloat16* g, int ld, int rows) {
    uint32_t sb = smem_u32(s);
    for (int i = threadIdx.x; i < rows*8; i += 256) {
        int r = i >> 3, c = i & 7;
        cp16(sb + r*144 + c*16, g + (size_t)r*ld + c*8);
    }
}

// ===========================================================================
// static device scratch
// ===========================================================================
__device__ float          d_scores[BH_*(size_t)S_*S_];    // 537 MB
__device__ __nv_bfloat16  d_Ph[BH_*(size_t)S_*S_];        // 268 MB
__device__ __nv_bfloat16  d_Pl[BH_*(size_t)S_*S_];        // 268 MB
__device__ __nv_bfloat16  d_X3h[3*TOK_*E_], d_X3l[3*TOK_*E_];  // q/k/v inputs split
__device__ __nv_bfloat16  d_W3h[3*E_*E_],  d_W3l[3*E_*E_];     // Wq/Wk/Wv^T split
__device__ __nv_bfloat16  d_Wth[E_*E_],  d_Wtl[E_*E_];         // Wo^T split
__device__ __nv_bfloat16  d_Qh[BH_*S_*D_], d_Ql[BH_*S_*D_];
__device__ __nv_bfloat16  d_Kh[BH_*S_*D_], d_Kl[BH_*S_*D_];
__device__ __nv_bfloat16  d_Vh[BH_*S_*D_], d_Vl[BH_*S_*D_];
__device__ __nv_bfloat16  d_Ch[TOK_*E_],  d_Cl[TOK_*E_];       // ctx split [B,S,E]
__device__ float          d_mixsm[H_*H_];

// ===========================================================================
// 0) softmax of the 16x16 head-mixing matrix
// ===========================================================================
__global__ void mix_softmax_kernel(const float* __restrict__ hm) {
    int g = threadIdx.x;
    if (g >= H_) return;
    float m = -1e30f;
    #pragma unroll
    for (int h = 0; h < H_; h++) m = fmaxf(m, hm[g*H_ + h]);
    float e[H_]; float s = 0.f;
    #pragma unroll
    for (int h = 0; h < H_; h++) { e[h] = expf(hm[g*H_ + h] - m); s += e[h]; }
    float inv = 1.f / s;
    #pragma unroll
    for (int h = 0; h < H_; h++) d_mixsm[g*H_ + h] = e[h] * inv;
}

// ===========================================================================
// 1) fp32 -> split-bf16, 3 tensors in one launch (z selects)
// ===========================================================================
__global__ __launch_bounds__(256) void split_f3(const float* __restrict__ q,
        const float* __restrict__ k, const float* __restrict__ v, int n4) {
    int z = blockIdx.z;
    const float* in = (z == 0) ? q : (z == 1) ? k : v;
    __nv_bfloat16* oh = d_X3h + (size_t)z*TOK_*E_;
    __nv_bfloat16* ol = d_X3l + (size_t)z*TOK_*E_;
    int i = blockIdx.x*256 + threadIdx.x;
    if (i >= n4) return;
    float4 vv = ((const float4*)in)[i];
    __nv_bfloat16 h0,h1,h2,h3,l0,l1,l2,l3;
    split2(vv.x,h0,l0); split2(vv.y,h1,l1); split2(vv.z,h2,l2); split2(vv.w,h3,l3);
    __nv_bfloat162 p;
    p.x=h0; p.y=h1; ((__nv_bfloat162*)oh)[2*i]   = p;
    p.x=h2; p.y=h3; ((__nv_bfloat162*)oh)[2*i+1] = p;
    p.x=l0; p.y=l1; ((__nv_bfloat162*)ol)[2*i]   = p;
    p.x=l2; p.y=l3; ((__nv_bfloat162*)ol)[2*i+1] = p;
}

// ===========================================================================
// 2) W [K,N] fp32 -> W^T [N,K] split-bf16. wt3: 3 weights in one launch.
// ===========================================================================
__device__ __forceinline__ void wt_body(const float* __restrict__ W,
        __nv_bfloat16* __restrict__ oh, __nv_bfloat16* __restrict__ ol) {
    __shared__ float t[32][33];
    int n0 = blockIdx.x*32, k0 = blockIdx.y*32;
    int tx = threadIdx.x, ty = threadIdx.y;
    #pragma unroll
    for (int i = 0; i < 4; i++)
        t[ty+8*i][tx] = W[(size_t)(k0+ty+8*i)*E_ + n0+tx];
    __syncthreads();
    #pragma unroll
    for (int i = 0; i < 4; i++) {
        float v = t[tx][ty+8*i];
        size_t idx = (size_t)(n0+ty+8*i)*E_ + k0 + tx;
        __nv_bfloat16 hb, lb; split2(v, hb, lb);
        oh[idx] = hb; ol[idx] = lb;
    }
}
__global__ void split_wt3(const float* __restrict__ Wq,
        const float* __restrict__ Wk, const float* __restrict__ Wv) {
    int z = blockIdx.z;
    const float* W = (z == 0) ? Wq : (z == 1) ? Wk : Wv;
    wt_body(W, d_W3h + (size_t)z*E_*E_, d_W3l + (size_t)z*E_*E_);
}
__global__ void split_wt(const float* __restrict__ W) {
    wt_body(W, d_Wth, d_Wtl);
}

// ===========================================================================
// 3a) QKV projection GEMM, z in {0,1,2} selects tensor. 128x128 block.
//     Epilogue: split-bf16 [B,H,S,D].
// ===========================================================================
#define PROJ_SMEM (2*4*10240)   // 81920
__global__ __launch_bounds__(256) void gemm_qkv(
    const float* __restrict__ bq, const float* __restrict__ bk,
    const float* __restrict__ bv)
{
    char* sm = dynsm;
    const int z = blockIdx.z;
    const float* bias = (z == 0) ? bq : (z == 1) ? bk : bv;
    __nv_bfloat16* outH = (z == 0) ? d_Qh : (z == 1) ? d_Kh : d_Vh;
    __nv_bfloat16* outL = (z == 0) ? d_Ql : (z == 1) ? d_Kl : d_Vl;
    const __nv_bfloat16* Ah_ = d_X3h + (size_t)z*TOK_*E_;
    const __nv_bfloat16* Al_ = d_X3l + (size_t)z*TOK_*E_;
    const __nv_bfloat16* Bh_ = d_W3h + (size_t)z*E_*E_;
    const __nv_bfloat16* Bl_ = d_W3l + (size_t)z*E_*E_;

    const int tid = threadIdx.x, lane = tid & 31, wid = tid >> 5;
    const int wm = wid >> 1, wn = wid & 1;
    const int g = lane >> 2, tg = lane & 3;
    const int bm = blockIdx.y*128, bn = blockIdx.x*128;

    float acc[2][8][4];
    #pragma unroll
    for (int i = 0; i < 2; i++)
        #pragma unroll
        for (int j = 0; j < 8; j++)
            #pragma unroll
            for (int q = 0; q < 4; q++) acc[i][j][q] = 0.f;

    const __nv_bfloat16* gT[4] = { Ah_ + (size_t)bm*E_, Al_ + (size_t)bm*E_,
                                   Bh_ + (size_t)bn*E_, Bl_ + (size_t)bn*E_ };
    #pragma unroll
    for (int t = 0; t < 4; t++) ld_chunk32(sm + t*10240, gT[t], E_, 128);
    CP_COMMIT();

    for (int c = 0; c < 32; c++) {
        if (c < 31) {
            int k0 = (c+1)*32;
            char* st = sm + ((c+1)&1)*40960;
            #pragma unroll
            for (int t = 0; t < 4; t++) ld_chunk32(st + t*10240, gT[t] + k0, E_, 128);
            CP_COMMIT(); CP_WAIT1();
        } else CP_WAIT0();
        __syncthreads();
        const char* st = sm + (c&1)*40960;
        #pragma unroll
        for (int ks = 0; ks < 2; ks++) {
            int kb = ks*32 + tg*4;
            uint32_t aH[2][4], aL[2][4], bH[8][2], bL[8][2];
            #pragma unroll
            for (int i = 0; i < 2; i++) {
                int r0 = wm*32 + i*16 + g;
                lda4(aH[i], st,          80, r0, kb);
                lda4(aL[i], st + 10240,  80, r0, kb);
            }
            #pragma unroll
            for (int j = 0; j < 8; j++) {
                int n = wn*64 + j*8 + g;
                ldb2(bH[j], st + 20480, 80, n, kb);
                ldb2(bL[j], st + 30720, 80, n, kb);
            }
            #pragma unroll
            for (int i = 0; i < 2; i++)
                #pragma unroll
                for (int j = 0; j < 8; j++) {
                    mma_bf16(acc[i][j], aH[i], bH[j]);
                    mma_bf16(acc[i][j], aH[i], bL[j]);
                    mma_bf16(acc[i][j], aL[i], bH[j]);
                }
        }
        __syncthreads();
    }

    #pragma unroll
    for (int j = 0; j < 8; j++) {
        int c = bn + wn*64 + j*8 + tg*2;
        float b0 = bias[c], b1 = bias[c+1];
        #pragma unroll
        for (int i = 0; i < 2; i++) {
            #pragma unroll
            for (int half = 0; half < 2; half++) {
                int r = bm + wm*32 + i*16 + g + half*8;
                float v0 = acc[i][j][half*2+0] + b0;
                float v1 = acc[i][j][half*2+1] + b1;
                int bb = r >> 11, s = r & (S_-1);
                int h = c >> 6,  d = c & 63;
                __nv_bfloat16 h0,l0,h1,l1;
                split2(v0,h0,l0); split2(v1,h1,l1);
                size_t idx = (((size_t)bb*H_ + h)*S_ + s)*D_ + d;
                __nv_bfloat162 ph; ph.x=h0; ph.y=h1;
                __nv_bfloat162 pl; pl.x=l0; pl.y=l1;
                *(__nv_bfloat162*)&outH[idx] = ph;
                *(__nv_bfloat162*)&outL[idx] = pl;
            }
        }
    }
}

// ===========================================================================
// 3b) output projection GEMM: out[4096,1024] fp32 = C @ Wo^T + bo
// ===========================================================================
__global__ __launch_bounds__(256) void gemm_out(
    const float* __restrict__ bias, float* __restrict__ outF)
{
    char* sm = dynsm;
    const int tid = threadIdx.x, lane = tid & 31, wid = tid >> 5;
    const int wm = wid >> 1, wn = wid & 1;
    const int g = lane >> 2, tg = lane & 3;
    const int bm = blockIdx.y*128, bn = blockIdx.x*128;

    float acc[2][8][4];
    #pragma unroll
    for (int i = 0; i < 2; i++)
        #pragma unroll
        for (int j = 0; j < 8; j++)
            #pragma unroll
            for (int q = 0; q < 4; q++) acc[i][j][q] = 0.f;

    const __nv_bfloat16* gT[4] = { d_Ch + (size_t)bm*E_, d_Cl + (size_t)bm*E_,
                                   d_Wth + (size_t)bn*E_, d_Wtl + (size_t)bn*E_ };
    #pragma unroll
    for (int t = 0; t < 4; t++) ld_chunk32(sm + t*10240, gT[t], E_, 128);
    CP_COMMIT();

    for (int c = 0; c < 32; c++) {
        if (c < 31) {
            int k0 = (c+1)*32;
            char* st = sm + ((c+1)&1)*40960;
            #pragma unroll
            for (int t = 0; t < 4; t++) ld_chunk32(st + t*10240, gT[t] + k0, E_, 128);
            CP_COMMIT(); CP_WAIT1();
        } else CP_WAIT0();
        __syncthreads();
        const char* st = sm + (c&1)*40960;
        #pragma unroll
        for (int ks = 0; ks < 2; ks++) {
            int kb = ks*32 + tg*4;
            uint32_t aH[2][4], aL[2][4], bH[8][2], bL[8][2];
            #pragma unroll
            for (int i = 0; i < 2; i++) {
                int r0 = wm*32 + i*16 + g;
                lda4(aH[i], st,          80, r0, kb);
                lda4(aL[i], st + 10240,  80, r0, kb);
            }
            #pragma unroll
            for (int j = 0; j < 8; j++) {
                int n = wn*64 + j*8 + g;
                ldb2(bH[j], st + 20480, 80, n, kb);
                ldb2(bL[j], st + 30720, 80, n, kb);
            }
            #pragma unroll
            for (int i = 0; i < 2; i++)
                #pragma unroll
                for (int j = 0; j < 8; j++) {
                    mma_bf16(acc[i][j], aH[i], bH[j]);
                    mma_bf16(acc[i][j], aH[i], bL[j]);
                    mma_bf16(acc[i][j], aL[i], bH[j]);
                }
        }
        __syncthreads();
    }

    #pragma unroll
    for (int j = 0; j < 8; j++) {
        int c = bn + wn*64 + j*8 + tg*2;
        float b0 = bias[c], b1 = bias[c+1];
        #pragma unroll
        for (int i = 0; i < 2; i++) {
            #pragma unroll
            for (int half = 0; half < 2; half++) {
                int r = bm + wm*32 + i*16 + g + half*8;
                float2 f;
                f.x = acc[i][j][half*2+0] + b0;
                f.y = acc[i][j][half*2+1] + b1;
                *(float2*)&outF[(size_t)r*E_ + c] = f;
            }
        }
    }
}

// ===========================================================================
// 4) scores = Q K^T / 8 per (b,h). 128x128 block, K=64 single-shot.
// ===========================================================================
#define SC_SMEM (4*18432)   // 73728
__global__ __launch_bounds__(256) void scores_mma()
{
    char* sm = dynsm;
    const int tid = threadIdx.x, lane = tid & 31, wid = tid >> 5;
    const int wm = wid >> 1, wn = wid & 1;
    const int g = lane >> 2, tg = lane & 3;
    const int bh = blockIdx.z;
    const int bm = blockIdx.y*128, bn = blockIdx.x*128;

    ld_chunk64(sm,           d_Qh + (size_t)bh*S_*D_ + (size_t)bm*D_, D_, 128);
    ld_chunk64(sm + 18432,   d_Ql + (size_t)bh*S_*D_ + (size_t)bm*D_, D_, 128);
    ld_chunk64(sm + 36864,   d_Kh + (size_t)bh*S_*D_ + (size_t)bn*D_, D_, 128);
    ld_chunk64(sm + 55296,   d_Kl + (size_t)bh*S_*D_ + (size_t)bn*D_, D_, 128);
    CP_COMMIT(); CP_WAIT0();
    __syncthreads();

    float acc[2][8][4];
    #pragma unroll
    for (int i = 0; i < 2; i++)
        #pragma unroll
        for (int j = 0; j < 8; j++)
            #pragma unroll
            for (int q = 0; q < 4; q++) acc[i][j][q] = 0.f;

    #pragma unroll
    for (int ks = 0; ks < 4; ks++) {
        int kb = ks*32 + tg*4;
        uint32_t aH[2][4], aL[2][4], bH[8][2], bL[8][2];
        #pragma unroll
        for (int i = 0; i < 2; i++) {
            int r0 = wm*32 + i*16 + g;
            lda4(aH[i], sm,         144, r0, kb);
            lda4(aL[i], sm + 18432, 144, r0, kb);
        }
        #pragma unroll
        for (int j = 0; j < 8; j++) {
            int n = wn*64 + j*8 + g;
            ldb2(bH[j], sm + 36864, 144, n, kb);
            ldb2(bL[j], sm + 55296, 144, n, kb);
        }
        #pragma unroll
        for (int i = 0; i < 2; i++)
            #pragma unroll
            for (int j = 0; j < 8; j++) {
                mma_bf16(acc[i][j], aH[i], bH[j]);
                mma_bf16(acc[i][j], aH[i], bL[j]);
                mma_bf16(acc[i][j], aL[i], bH[j]);
            }
    }

    float* outb = d_scores + (size_t)bh*S_*S_;
    #pragma unroll
    for (int i = 0; i < 2; i++)
        #pragma unroll
        for (int j = 0; j < 8; j++) {
            int c = bn + wn*64 + j*8 + tg*2;
            #pragma unroll
            for (int half = 0; half < 2; half++) {
                int r = bm + wm*32 + i*16 + g + half*8;
                float2 f;
                f.x = acc[i][j][half*2+0] * 0.125f;
                f.y = acc[i][j][half*2+1] * 0.125f;
                *(float2*)&outb[(size_t)r*S_ + c] = f;
            }
        }
}

// ===========================================================================
// 5) fused row-softmax + head mixing. Block per (b,q); emits split-bf16 P
//    with 4-byte bf16x2 stores (layout identical to 2x bf16).
// ===========================================================================
#define SMX_SMEM ((H_*S_ + 16 + 256)*4)   // 132160
__global__ __launch_bounds__(256) void softmax_mix_kernel()
{
    float* sm   = (float*)dynsm;
    float* inv  = sm + H_*S_;
    float* mixs = inv + 16;
    const int bq = blockIdx.x;
    const int b = bq >> 11, q = bq & (S_-1);
    const int tid = threadIdx.x;

    const float* src = d_scores + ((size_t)b*H_)*S_*S_ + (size_t)q*S_;
    for (int i = tid; i < H_*S_/4; i += 256) {
        int h = i >> 9, k4 = i & 511;
        ((float4*)sm)[i] = *(const float4*)(src + (size_t)h*S_*S_ + k4*4);
    }
    mixs[tid] = d_mixsm[tid & 255];
    __syncthreads();

    int w = tid >> 5, lane = tid & 31;
    #pragma unroll
    for (int hh = 0; hh < 2; hh++) {
        int h = w*2 + hh;
        float* row = sm + h*S_;
        float m = -1e30f;
        for (int j = lane; j < S_; j += 32) m = fmaxf(m, row[j]);
        #pragma unroll
        for (int o = 16; o; o >>= 1) m = fmaxf(m, __shfl_xor_sync(0xFFFFFFFFu, m, o));
        float s = 0.f;
        for (int j = lane; j < S_; j += 32) { float e = __expf(row[j] - m); row[j] = e; s += e; }
        #pragma unroll
        for (int o = 16; o; o >>= 1) s += __shfl_xor_sync(0xFFFFFFFFu, s, o);
        if (lane == 0) inv[h] = 1.f / s;
    }
    __syncthreads();

    size_t obase = ((size_t)b*H_)*S_*S_ + (size_t)q*S_;
    for (int k2 = tid; k2 < S_/2; k2 += 256) {
        int k0 = k2*2;
        float a0[H_], a1[H_];
        #pragma unroll
        for (int h = 0; h < H_; h++) {
            a0[h] = sm[h*S_ + k0]     * inv[h];
            a1[h] = sm[h*S_ + k0 + 1] * inv[h];
        }
        #pragma unroll
        for (int g = 0; g < H_; g++) {
            float o0 = 0.f, o1 = 0.f;
            #pragma unroll
            for (int h = 0; h < H_; h++) {
                o0 = fmaf(mixs[g*16 + h], a0[h], o0);
                o1 = fmaf(mixs[g*16 + h], a1[h], o1);
            }
            __nv_bfloat16 h0, l0, h1, l1;
            split2(o0, h0, l0); split2(o1, h1, l1);
            size_t idx = obase + (size_t)g*S_*S_ + k0;
            __nv_bfloat162 ph; ph.x = h0; ph.y = h1;
            __nv_bfloat162 pl; pl.x = l0; pl.y = l1;
            *(__nv_bfloat162*)&d_Ph[idx] = ph;
            *(__nv_bfloat162*)&d_Pl[idx] = pl;
        }
    }
}

// ===========================================================================
// 6) ctx = P @ V per (b,g). 128x64 block, 8 warps @ 32x32, K=2048.
// ===========================================================================
#define CTX_STAGE (2*10240 + 2*4608)      // 29696
#define CTX_SMEM  (2*CTX_STAGE)           // 59392
__global__ __launch_bounds__(256) void ctx_mma()
{
    char* sm = dynsm;
    const int tid = threadIdx.x, lane = tid & 31, wid = tid >> 5;
    const int wm = wid >> 1, wn = wid & 1;
    const int g = lane >> 2, tg = lane & 3;
    const int bg = blockIdx.y;
    const int b = bg >> 4, ghead = bg & 15;
    const int bm = blockIdx.x*128;

    const __nv_bfloat16* ph = d_Ph + (size_t)bg*S_*S_ + (size_t)bm*S_;
    const __nv_bfloat16* pl = d_Pl + (size_t)bg*S_*S_ + (size_t)bm*S_;
    const __nv_bfloat16* vh = d_Vh + (size_t)bg*S_*D_;
    const __nv_bfloat16* vl = d_Vl + (size_t)bg*S_*D_;

    float acc[2][4][4];
    #pragma unroll
    for (int i = 0; i < 2; i++)
        #pragma unroll
        for (int j = 0; j < 4; j++)
            #pragma unroll
            for (int q = 0; q < 4; q++) acc[i][j][q] = 0.f;

    {   // preload chunk 0
        char* st = sm;
        ld_chunk32(st,         ph, S_, 128);
        ld_chunk32(st + 10240, pl, S_, 128);
        ld_chunk64(st + 20480, vh, D_, 32);
        ld_chunk64(st + 25088, vl, D_, 32);
        CP_COMMIT();
    }
    for (int c = 0; c < 64; c++) {
        if (c < 63) {
            int k0 = (c+1)*32;
            char* st = sm + ((c+1)&1)*CTX_STAGE;
            ld_chunk32(st,         ph + k0, S_, 128);
            ld_chunk32(st + 10240, pl + k0, S_, 128);
            ld_chunk64(st + 20480, vh + (size_t)k0*D_, D_, 32);
            ld_chunk64(st + 25088, vl + (size_t)k0*D_, D_, 32);
            CP_COMMIT(); CP_WAIT1();
        } else CP_WAIT0();
        __syncthreads();
        const char* st = sm + (c&1)*CTX_STAGE;
        const char* vH = st + 20480;
        const char* vL = st + 25088;
        #pragma unroll
        for (int ks = 0; ks < 2; ks++) {
            int kb = ks*32 + tg*4;
            uint32_t aH[2][4], aL[2][4], bH[4][2], bL[4][2];
            #pragma unroll
            for (int i = 0; i < 2; i++) {
                int r0 = wm*32 + i*16 + g;
                lda4(aH[i], st,         80, r0, kb);
                lda4(aL[i], st + 10240, 80, r0, kb);
            }
            int krow = ks*16 + tg*2;
            #pragma unroll
            for (int j = 0; j < 4; j++) {
                int n2 = (wn*32 + j*8 + g)*2;
                uint32_t x0, x1, x2, x3;
                x0 = *(const unsigned short*)(vH + (krow  )*144 + n2);
                x1 = *(const unsigned short*)(vH + (krow+1)*144 + n2);
                x2 = *(const unsigned short*)(vH + (krow+8)*144 + n2);
                x3 = *(const unsigned short*)(vH + (krow+9)*144 + n2);
                bH[j][0] = x0 | (x1 << 16);
                bH[j][1] = x2 | (x3 << 16);
                x0 = *(const unsigned short*)(vL + (krow  )*144 + n2);
                x1 = *(const unsigned short*)(vL + (krow+1)*144 + n2);
                x2 = *(const unsigned short*)(vL + (krow+8)*144 + n2);
                x3 = *(const unsigned short*)(vL + (krow+9)*144 + n2);
                bL[j][0] = x0 | (x1 << 16);
                bL[j][1] = x2 | (x3 << 16);
            }
            #pragma unroll
            for (int i = 0; i < 2; i++)
                #pragma unroll
                for (int j = 0; j < 4; j++) {
                    mma_bf16(acc[i][j], aH[i], bH[j]);
                    mma_bf16(acc[i][j], aH[i], bL[j]);
                    mma_bf16(acc[i][j], aL[i], bH[j]);
                }
        }
        __syncthreads();
    }

    #pragma unroll
    for (int i = 0; i < 2; i++)
        #pragma unroll
        for (int j = 0; j < 4; j++) {
            int d = wn*32 + j*8 + tg*2;
            #pragma unroll
            for (int half = 0; half < 2; half++) {
                int q = bm + wm*32 + i*16 + g + half*8;
                float v0 = acc[i][j][half*2+0];
                float v1 = acc[i][j][half*2+1];
                __nv_bfloat16 h0,l0,h1,l1;
                split2(v0,h0,l0); split2(v1,h1,l1);
                size_t idx = ((size_t)b*S_ + q)*E_ + ghead*D_ + d;
                __nv_bfloat162 ph2; ph2.x=h0; ph2.y=h1;
                __nv_bfloat162 pl2; pl2.x=l0; pl2.y=l1;
                *(__nv_bfloat162*)&d_Ch[idx] = ph2;
                *(__nv_bfloat162*)&d_Cl[idx] = pl2;
            }
        }
}

// ===========================================================================
// kernel_launch
// ===========================================================================
extern "C" void kernel_launch(void* const* d_in, const int* in_sizes, int n_in,
                              void* d_out, int out_size)
{
    (void)in_sizes; (void)n_in; (void)out_size;
    const float* query = (const float*)d_in[0];
    const float* key_  = (const float*)d_in[1];
    const float* value = (const float*)d_in[2];
    const float* Wq = (const float*)d_in[3];
    const float* bq = (const float*)d_in[4];
    const float* Wk = (const float*)d_in[5];
    const float* bk = (const float*)d_in[6];
    const float* Wv = (const float*)d_in[7];
    const float* bv = (const float*)d_in[8];
    const float* hm = (const float*)d_in[9];
    const float* Wo = (const float*)d_in[10];
    const float* bo = (const float*)d_in[11];
    float* out = (float*)d_out;

    cudaFuncSetAttribute(gemm_qkv,           cudaFuncAttributeMaxDynamicSharedMemorySize, PROJ_SMEM);
    cudaFuncSetAttribute(gemm_out,           cudaFuncAttributeMaxDynamicSharedMemorySize, PROJ_SMEM);
    cudaFuncSetAttribute(scores_mma,         cudaFuncAttributeMaxDynamicSharedMemorySize, SC_SMEM);
    cudaFuncSetAttribute(softmax_mix_kernel, cudaFuncAttributeMaxDynamicSharedMemorySize, SMX_SMEM);
    cudaFuncSetAttribute(ctx_mma,            cudaFuncAttributeMaxDynamicSharedMemorySize, CTX_SMEM);

    const int n4 = TOK_*E_/4;

    mix_softmax_kernel<<<1, 16>>>(hm);
    split_wt3<<<dim3(32, 32, 3), dim3(32, 8)>>>(Wq, Wk, Wv);
    split_f3<<<dim3(n4/256, 1, 3), 256>>>(query, key_, value, n4);
    gemm_qkv<<<dim3(E_/128, TOK_/128, 3), 256, PROJ_SMEM>>>(bq, bk, bv);

    scores_mma<<<dim3(S_/128, S_/128, BH_), 256, SC_SMEM>>>();   // (16,16,32)
    softmax_mix_kernel<<<B_*S_, 256, SMX_SMEM>>>();              // 4096 blocks
    ctx_mma<<<dim3(S_/128, BH_), 256, CTX_SMEM>>>();             // (16,32)

    split_wt<<<dim3(32, 32), dim3(32, 8)>>>(Wo);
    gemm_out<<<dim3(E_/128, TOK_/128), 256, PROJ_SMEM>>>(bo, out);
}

// round 10
// speedup vs baseline: 1.6786x; 1.1659x over previous
#include <cuda_runtime.h>
#include <cuda_bf16.h>
#include <cuda_fp16.h>
#include <cstdint>

#define B_   2
#define S_   2048
#define E_   1024
#define H_   16
#define D_   64
#define BH_  (B_*H_)      // 32
#define TOK_ (B_*S_)      // 4096

// single dynamic-smem symbol shared by all kernels
extern __shared__ __align__(16) char dynsm[];

// ===========================================================================
// helpers
// ===========================================================================
__device__ __forceinline__ uint32_t smem_u32(const void* p) {
    uint32_t a;
    asm("{ .reg .u64 t; cvta.to.shared.u64 t, %1; cvt.u32.u64 %0, t; }" : "=r"(a) : "l"(p));
    return a;
}
#define CP_COMMIT()  asm volatile("cp.async.commit_group;" ::: "memory")
#define CP_WAIT0()   asm volatile("cp.async.wait_group 0;" ::: "memory")
#define CP_WAIT1()   asm volatile("cp.async.wait_group 1;" ::: "memory")

__device__ __forceinline__ void cp16(uint32_t dst, const void* src) {
    asm volatile("cp.async.cg.shared.global [%0], [%1], 16;" :: "r"(dst), "l"(src) : "memory");
}

// m16n8k16 bf16 MMA, fp32 accum. A row-major, B col-major ([n][k] row-major).
__device__ __forceinline__ void mma_bf16(float c[4], const uint32_t a[4], const uint32_t b[2]) {
    asm volatile("mma.sync.aligned.m16n8k16.row.col.f32.bf16.bf16.f32 "
        "{%0,%1,%2,%3}, {%4,%5,%6,%7}, {%8,%9}, {%0,%1,%2,%3};"
        : "+f"(c[0]), "+f"(c[1]), "+f"(c[2]), "+f"(c[3])
        : "r"(a[0]), "r"(a[1]), "r"(a[2]), "r"(a[3]), "r"(b[0]), "r"(b[1]));
}
// m16n8k16 fp16 MMA, fp32 accum.
__device__ __forceinline__ void mma_f16(float c[4], const uint32_t a[4], const uint32_t b[2]) {
    asm volatile("mma.sync.aligned.m16n8k16.row.col.f32.f16.f16.f32 "
        "{%0,%1,%2,%3}, {%4,%5,%6,%7}, {%8,%9}, {%0,%1,%2,%3};"
        : "+f"(c[0]), "+f"(c[1]), "+f"(c[2]), "+f"(c[3])
        : "r"(a[0]), "r"(a[1]), "r"(a[2]), "r"(a[3]), "r"(b[0]), "r"(b[1]));
}

__device__ __forceinline__ void split2(float v, __nv_bfloat16& h, __nv_bfloat16& l) {
    h = __float2bfloat16(v);
    l = __float2bfloat16(v - __bfloat162float(h));
}

// A-fragment from a row-major smem tile (stride bytes), rows r0/r0+8, k-bytes kb
__device__ __forceinline__ void lda4(uint32_t a[4], const char* t, int stride, int r0, int kb) {
    a[0] = *(const uint32_t*)(t + (size_t)(r0    )*stride + kb);
    a[1] = *(const uint32_t*)(t + (size_t)(r0 + 8)*stride + kb);
    a[2] = *(const uint32_t*)(t + (size_t)(r0    )*stride + kb + 16);
    a[3] = *(const uint32_t*)(t + (size_t)(r0 + 8)*stride + kb + 16);
}
// B-fragment from [n][k] row-major tile
__device__ __forceinline__ void ldb2(uint32_t b[2], const char* t, int stride, int n, int kb) {
    b[0] = *(const uint32_t*)(t + (size_t)n*stride + kb);
    b[1] = *(const uint32_t*)(t + (size_t)n*stride + kb + 16);
}

// load [rows x 32] 16-bit-elem chunk -> smem rows of 80 bytes (64 B + 16 pad)
__device__ __forceinline__ void ld_chunk32(char* s, const void* g, int ld, int rows) {
    uint32_t sb = smem_u32(s);
    const char* gb = (const char*)g;
    for (int i = threadIdx.x; i < rows*4; i += 256) {
        int r = i >> 2, c = i & 3;
        cp16(sb + r*80 + c*16, gb + (size_t)r*ld*2 + c*16);
    }
}
// load [rows x 64] 16-bit-elem chunk -> smem rows of 144 bytes (128 B + 16 pad)
__device__ __forceinline__ void ld_chunk64(char* s, const void* g, int ld, int rows) {
    uint32_t sb = smem_u32(s);
    const char* gb = (const char*)g;
    for (int i = threadIdx.x; i < rows*8; i += 256) {
        int r = i >> 3, c = i & 7;
        cp16(sb + r*144 + c*16, gb + (size_t)r*ld*2 + c*16);
    }
}

// ===========================================================================
// static device scratch
// ===========================================================================
__device__ float          d_scores[BH_*(size_t)S_*S_];    // 537 MB
__device__ __half         d_Pf[BH_*(size_t)S_*S_];        // 268 MB fp16 P
__device__ __nv_bfloat16  d_X3h[3*TOK_*E_], d_X3l[3*TOK_*E_];  // q/k/v inputs split
__device__ __nv_bfloat16  d_W3h[3*E_*E_],  d_W3l[3*E_*E_];     // Wq/Wk/Wv^T split
__device__ __nv_bfloat16  d_Wth[E_*E_],  d_Wtl[E_*E_];         // Wo^T split
__device__ __nv_bfloat16  d_Qh[BH_*S_*D_], d_Ql[BH_*S_*D_];
__device__ __nv_bfloat16  d_Kh[BH_*S_*D_], d_Kl[BH_*S_*D_];
__device__ __half         d_Vf[BH_*S_*D_];                     // fp16 V
__device__ __nv_bfloat16  d_Ch[TOK_*E_],  d_Cl[TOK_*E_];       // ctx split [B,S,E]
__device__ float          d_mixsm[H_*H_];

// ===========================================================================
// 0) softmax of the 16x16 head-mixing matrix
// ===========================================================================
__global__ void mix_softmax_kernel(const float* __restrict__ hm) {
    int g = threadIdx.x;
    if (g >= H_) return;
    float m = -1e30f;
    #pragma unroll
    for (int h = 0; h < H_; h++) m = fmaxf(m, hm[g*H_ + h]);
    float e[H_]; float s = 0.f;
    #pragma unroll
    for (int h = 0; h < H_; h++) { e[h] = expf(hm[g*H_ + h] - m); s += e[h]; }
    float inv = 1.f / s;
    #pragma unroll
    for (int h = 0; h < H_; h++) d_mixsm[g*H_ + h] = e[h] * inv;
}

// ===========================================================================
// 1) fp32 -> split-bf16, 3 tensors in one launch (z selects)
// ===========================================================================
__global__ __launch_bounds__(256) void split_f3(const float* __restrict__ q,
        const float* __restrict__ k, const float* __restrict__ v, int n4) {
    int z = blockIdx.z;
    const float* in = (z == 0) ? q : (z == 1) ? k : v;
    __nv_bfloat16* oh = d_X3h + (size_t)z*TOK_*E_;
    __nv_bfloat16* ol = d_X3l + (size_t)z*TOK_*E_;
    int i = blockIdx.x*256 + threadIdx.x;
    if (i >= n4) return;
    float4 vv = ((const float4*)in)[i];
    __nv_bfloat16 h0,h1,h2,h3,l0,l1,l2,l3;
    split2(vv.x,h0,l0); split2(vv.y,h1,l1); split2(vv.z,h2,l2); split2(vv.w,h3,l3);
    __nv_bfloat162 p;
    p.x=h0; p.y=h1; ((__nv_bfloat162*)oh)[2*i]   = p;
    p.x=h2; p.y=h3; ((__nv_bfloat162*)oh)[2*i+1] = p;
    p.x=l0; p.y=l1; ((__nv_bfloat162*)ol)[2*i]   = p;
    p.x=l2; p.y=l3; ((__nv_bfloat162*)ol)[2*i+1] = p;
}

// ===========================================================================
// 2) W [K,N] fp32 -> W^T [N,K] split-bf16. wt3: 3 weights in one launch.
// ===========================================================================
__device__ __forceinline__ void wt_body(const float* __restrict__ W,
        __nv_bfloat16* __restrict__ oh, __nv_bfloat16* __restrict__ ol) {
    __shared__ float t[32][33];
    int n0 = blockIdx.x*32, k0 = blockIdx.y*32;
    int tx = threadIdx.x, ty = threadIdx.y;
    #pragma unroll
    for (int i = 0; i < 4; i++)
        t[ty+8*i][tx] = W[(size_t)(k0+ty+8*i)*E_ + n0+tx];
    __syncthreads();
    #pragma unroll
    for (int i = 0; i < 4; i++) {
        float v = t[tx][ty+8*i];
        size_t idx = (size_t)(n0+ty+8*i)*E_ + k0 + tx;
        __nv_bfloat16 hb, lb; split2(v, hb, lb);
        oh[idx] = hb; ol[idx] = lb;
    }
}
__global__ void split_wt3(const float* __restrict__ Wq,
        const float* __restrict__ Wk, const float* __restrict__ Wv) {
    int z = blockIdx.z;
    const float* W = (z == 0) ? Wq : (z == 1) ? Wk : Wv;
    wt_body(W, d_W3h + (size_t)z*E_*E_, d_W3l + (size_t)z*E_*E_);
}
__global__ void split_wt(const float* __restrict__ W) {
    wt_body(W, d_Wth, d_Wtl);
}

// ===========================================================================
// 3a) QKV projection GEMM, z in {0,1,2}. 128x128 block, 8 warps @ 32x64.
//     Epilogue: Q,K split-bf16 [B,H,S,D]; V fp16 [B,H,S,D].
// ===========================================================================
#define PROJ_SMEM (2*4*10240)   // 81920
__global__ __launch_bounds__(256) void gemm_qkv(
    const float* __restrict__ bq, const float* __restrict__ bk,
    const float* __restrict__ bv)
{
    char* sm = dynsm;
    const int z = blockIdx.z;
    const float* bias = (z == 0) ? bq : (z == 1) ? bk : bv;
    __nv_bfloat16* outH = (z == 0) ? d_Qh : d_Kh;
    __nv_bfloat16* outL = (z == 0) ? d_Ql : d_Kl;
    const __nv_bfloat16* Ah_ = d_X3h + (size_t)z*TOK_*E_;
    const __nv_bfloat16* Al_ = d_X3l + (size_t)z*TOK_*E_;
    const __nv_bfloat16* Bh_ = d_W3h + (size_t)z*E_*E_;
    const __nv_bfloat16* Bl_ = d_W3l + (size_t)z*E_*E_;

    const int tid = threadIdx.x, lane = tid & 31, wid = tid >> 5;
    const int wm = wid >> 1, wn = wid & 1;
    const int g = lane >> 2, tg = lane & 3;
    const int bm = blockIdx.y*128, bn = blockIdx.x*128;

    float acc[2][8][4];
    #pragma unroll
    for (int i = 0; i < 2; i++)
        #pragma unroll
        for (int j = 0; j < 8; j++)
            #pragma unroll
            for (int q = 0; q < 4; q++) acc[i][j][q] = 0.f;

    const __nv_bfloat16* gT[4] = { Ah_ + (size_t)bm*E_, Al_ + (size_t)bm*E_,
                                   Bh_ + (size_t)bn*E_, Bl_ + (size_t)bn*E_ };
    #pragma unroll
    for (int t = 0; t < 4; t++) ld_chunk32(sm + t*10240, gT[t], E_, 128);
    CP_COMMIT();

    for (int c = 0; c < 32; c++) {
        if (c < 31) {
            int k0 = (c+1)*32;
            char* st = sm + ((c+1)&1)*40960;
            #pragma unroll
            for (int t = 0; t < 4; t++) ld_chunk32(st + t*10240, gT[t] + k0, E_, 128);
            CP_COMMIT(); CP_WAIT1();
        } else CP_WAIT0();
        __syncthreads();
        const char* st = sm + (c&1)*40960;
        #pragma unroll
        for (int ks = 0; ks < 2; ks++) {
            int kb = ks*32 + tg*4;
            uint32_t aH[2][4], aL[2][4], bH[8][2], bL[8][2];
            #pragma unroll
            for (int i = 0; i < 2; i++) {
                int r0 = wm*32 + i*16 + g;
                lda4(aH[i], st,          80, r0, kb);
                lda4(aL[i], st + 10240,  80, r0, kb);
            }
            #pragma unroll
            for (int j = 0; j < 8; j++) {
                int n = wn*64 + j*8 + g;
                ldb2(bH[j], st + 20480, 80, n, kb);
                ldb2(bL[j], st + 30720, 80, n, kb);
            }
            #pragma unroll
            for (int i = 0; i < 2; i++)
                #pragma unroll
                for (int j = 0; j < 8; j++) {
                    mma_bf16(acc[i][j], aH[i], bH[j]);
                    mma_bf16(acc[i][j], aH[i], bL[j]);
                    mma_bf16(acc[i][j], aL[i], bH[j]);
                }
        }
        __syncthreads();
    }

    #pragma unroll
    for (int j = 0; j < 8; j++) {
        int c = bn + wn*64 + j*8 + tg*2;
        float b0 = bias[c], b1 = bias[c+1];
        #pragma unroll
        for (int i = 0; i < 2; i++) {
            #pragma unroll
            for (int half = 0; half < 2; half++) {
                int r = bm + wm*32 + i*16 + g + half*8;
                float v0 = acc[i][j][half*2+0] + b0;
                float v1 = acc[i][j][half*2+1] + b1;
                int bb = r >> 11, s = r & (S_-1);
                int h = c >> 6,  d = c & 63;
                size_t idx = (((size_t)bb*H_ + h)*S_ + s)*D_ + d;
                if (z == 2) {
                    *(__half2*)&d_Vf[idx] = __floats2half2_rn(v0, v1);
                } else {
                    __nv_bfloat16 h0,l0,h1,l1;
                    split2(v0,h0,l0); split2(v1,h1,l1);
                    __nv_bfloat162 ph; ph.x=h0; ph.y=h1;
                    __nv_bfloat162 pl; pl.x=l0; pl.y=l1;
                    *(__nv_bfloat162*)&outH[idx] = ph;
                    *(__nv_bfloat162*)&outL[idx] = pl;
                }
            }
        }
    }
}

// ===========================================================================
// 3b) output projection GEMM: out[4096,1024] fp32 = C @ Wo^T + bo
// ===========================================================================
__global__ __launch_bounds__(256) void gemm_out(
    const float* __restrict__ bias, float* __restrict__ outF)
{
    char* sm = dynsm;
    const int tid = threadIdx.x, lane = tid & 31, wid = tid >> 5;
    const int wm = wid >> 1, wn = wid & 1;
    const int g = lane >> 2, tg = lane & 3;
    const int bm = blockIdx.y*128, bn = blockIdx.x*128;

    float acc[2][8][4];
    #pragma unroll
    for (int i = 0; i < 2; i++)
        #pragma unroll
        for (int j = 0; j < 8; j++)
            #pragma unroll
            for (int q = 0; q < 4; q++) acc[i][j][q] = 0.f;

    const __nv_bfloat16* gT[4] = { d_Ch + (size_t)bm*E_, d_Cl + (size_t)bm*E_,
                                   d_Wth + (size_t)bn*E_, d_Wtl + (size_t)bn*E_ };
    #pragma unroll
    for (int t = 0; t < 4; t++) ld_chunk32(sm + t*10240, gT[t], E_, 128);
    CP_COMMIT();

    for (int c = 0; c < 32; c++) {
        if (c < 31) {
            int k0 = (c+1)*32;
            char* st = sm + ((c+1)&1)*40960;
            #pragma unroll
            for (int t = 0; t < 4; t++) ld_chunk32(st + t*10240, gT[t] + k0, E_, 128);
            CP_COMMIT(); CP_WAIT1();
        } else CP_WAIT0();
        __syncthreads();
        const char* st = sm + (c&1)*40960;
        #pragma unroll
        for (int ks = 0; ks < 2; ks++) {
            int kb = ks*32 + tg*4;
            uint32_t aH[2][4], aL[2][4], bH[8][2], bL[8][2];
            #pragma unroll
            for (int i = 0; i < 2; i++) {
                int r0 = wm*32 + i*16 + g;
                lda4(aH[i], st,          80, r0, kb);
                lda4(aL[i], st + 10240,  80, r0, kb);
            }
            #pragma unroll
            for (int j = 0; j < 8; j++) {
                int n = wn*64 + j*8 + g;
                ldb2(bH[j], st + 20480, 80, n, kb);
                ldb2(bL[j], st + 30720, 80, n, kb);
            }
            #pragma unroll
            for (int i = 0; i < 2; i++)
                #pragma unroll
                for (int j = 0; j < 8; j++) {
                    mma_bf16(acc[i][j], aH[i], bH[j]);
                    mma_bf16(acc[i][j], aH[i], bL[j]);
                    mma_bf16(acc[i][j], aL[i], bH[j]);
                }
        }
        __syncthreads();
    }

    #pragma unroll
    for (int j = 0; j < 8; j++) {
        int c = bn + wn*64 + j*8 + tg*2;
        float b0 = bias[c], b1 = bias[c+1];
        #pragma unroll
        for (int i = 0; i < 2; i++) {
            #pragma unroll
            for (int half = 0; half < 2; half++) {
                int r = bm + wm*32 + i*16 + g + half*8;
                float2 f;
                f.x = acc[i][j][half*2+0] + b0;
                f.y = acc[i][j][half*2+1] + b1;
                *(float2*)&outF[(size_t)r*E_ + c] = f;
            }
        }
    }
}

// ===========================================================================
// 4) scores = Q K^T / 8 per (b,h). 128x128 block, K=64 single-shot.
// ===========================================================================
#define SC_SMEM (4*18432)   // 73728
__global__ __launch_bounds__(256) void scores_mma()
{
    char* sm = dynsm;
    const int tid = threadIdx.x, lane = tid & 31, wid = tid >> 5;
    const int wm = wid >> 1, wn = wid & 1;
    const int g = lane >> 2, tg = lane & 3;
    const int bh = blockIdx.z;
    const int bm = blockIdx.y*128, bn = blockIdx.x*128;

    ld_chunk64(sm,           d_Qh + (size_t)bh*S_*D_ + (size_t)bm*D_, D_, 128);
    ld_chunk64(sm + 18432,   d_Ql + (size_t)bh*S_*D_ + (size_t)bm*D_, D_, 128);
    ld_chunk64(sm + 36864,   d_Kh + (size_t)bh*S_*D_ + (size_t)bn*D_, D_, 128);
    ld_chunk64(sm + 55296,   d_Kl + (size_t)bh*S_*D_ + (size_t)bn*D_, D_, 128);
    CP_COMMIT(); CP_WAIT0();
    __syncthreads();

    float acc[2][8][4];
    #pragma unroll
    for (int i = 0; i < 2; i++)
        #pragma unroll
        for (int j = 0; j < 8; j++)
            #pragma unroll
            for (int q = 0; q < 4; q++) acc[i][j][q] = 0.f;

    #pragma unroll
    for (int ks = 0; ks < 4; ks++) {
        int kb = ks*32 + tg*4;
        uint32_t aH[2][4], aL[2][4], bH[8][2], bL[8][2];
        #pragma unroll
        for (int i = 0; i < 2; i++) {
            int r0 = wm*32 + i*16 + g;
            lda4(aH[i], sm,         144, r0, kb);
            lda4(aL[i], sm + 18432, 144, r0, kb);
        }
        #pragma unroll
        for (int j = 0; j < 8; j++) {
            int n = wn*64 + j*8 + g;
            ldb2(bH[j], sm + 36864, 144, n, kb);
            ldb2(bL[j], sm + 55296, 144, n, kb);
        }
        #pragma unroll
        for (int i = 0; i < 2; i++)
            #pragma unroll
            for (int j = 0; j < 8; j++) {
                mma_bf16(acc[i][j], aH[i], bH[j]);
                mma_bf16(acc[i][j], aH[i], bL[j]);
                mma_bf16(acc[i][j], aL[i], bH[j]);
            }
    }

    float* outb = d_scores + (size_t)bh*S_*S_;
    #pragma unroll
    for (int i = 0; i < 2; i++)
        #pragma unroll
        for (int j = 0; j < 8; j++) {
            int c = bn + wn*64 + j*8 + tg*2;
            #pragma unroll
            for (int half = 0; half < 2; half++) {
                int r = bm + wm*32 + i*16 + g + half*8;
                float2 f;
                f.x = acc[i][j][half*2+0] * 0.125f;
                f.y = acc[i][j][half*2+1] * 0.125f;
                *(float2*)&outb[(size_t)r*S_ + c] = f;
            }
        }
}

// ===========================================================================
// 5) fused row-softmax + head mixing. Block per (b,q); emits fp16 P.
// ===========================================================================
#define SMX_SMEM ((H_*S_ + 16 + 256)*4)   // 132160
__global__ __launch_bounds__(256) void softmax_mix_kernel()
{
    float* sm   = (float*)dynsm;
    float* inv  = sm + H_*S_;
    float* mixs = inv + 16;
    const int bq = blockIdx.x;
    const int b = bq >> 11, q = bq & (S_-1);
    const int tid = threadIdx.x;

    const float* src = d_scores + ((size_t)b*H_)*S_*S_ + (size_t)q*S_;
    for (int i = tid; i < H_*S_/4; i += 256) {
        int h = i >> 9, k4 = i & 511;
        ((float4*)sm)[i] = *(const float4*)(src + (size_t)h*S_*S_ + k4*4);
    }
    mixs[tid] = d_mixsm[tid & 255];
    __syncthreads();

    int w = tid >> 5, lane = tid & 31;
    #pragma unroll
    for (int hh = 0; hh < 2; hh++) {
        int h = w*2 + hh;
        float* row = sm + h*S_;
        float m = -1e30f;
        for (int j = lane; j < S_; j += 32) m = fmaxf(m, row[j]);
        #pragma unroll
        for (int o = 16; o; o >>= 1) m = fmaxf(m, __shfl_xor_sync(0xFFFFFFFFu, m, o));
        float s = 0.f;
        for (int j = lane; j < S_; j += 32) { float e = __expf(row[j] - m); row[j] = e; s += e; }
        #pragma unroll
        for (int o = 16; o; o >>= 1) s += __shfl_xor_sync(0xFFFFFFFFu, s, o);
        if (lane == 0) inv[h] = 1.f / s;
    }
    __syncthreads();

    size_t obase = ((size_t)b*H_)*S_*S_ + (size_t)q*S_;
    for (int k2 = tid; k2 < S_/2; k2 += 256) {
        int k0 = k2*2;
        float a0[H_], a1[H_];
        #pragma unroll
        for (int h = 0; h < H_; h++) {
            a0[h] = sm[h*S_ + k0]     * inv[h];
            a1[h] = sm[h*S_ + k0 + 1] * inv[h];
        }
        #pragma unroll
        for (int g = 0; g < H_; g++) {
            float o0 = 0.f, o1 = 0.f;
            #pragma unroll
            for (int h = 0; h < H_; h++) {
                o0 = fmaf(mixs[g*16 + h], a0[h], o0);
                o1 = fmaf(mixs[g*16 + h], a1[h], o1);
            }
            size_t idx = obase + (size_t)g*S_*S_ + k0;
            *(__half2*)&d_Pf[idx] = __floats2half2_rn(o0, o1);
        }
    }
}

// ===========================================================================
// 6) ctx = P @ V per (b,g), fp16 single-product. 128x64 block, 8 warps.
// ===========================================================================
#define CTX_STAGE (10240 + 4608)          // 14848
#define CTX_SMEM  (2*CTX_STAGE)           // 29696
__global__ __launch_bounds__(256) void ctx_mma()
{
    char* sm = dynsm;
    const int tid = threadIdx.x, lane = tid & 31, wid = tid >> 5;
    const int wm = wid >> 1, wn = wid & 1;
    const int g = lane >> 2, tg = lane & 3;
    const int bg = blockIdx.y;
    const int b = bg >> 4, ghead = bg & 15;
    const int bm = blockIdx.x*128;

    const __half* pf = d_Pf + (size_t)bg*S_*S_ + (size_t)bm*S_;
    const __half* vf = d_Vf + (size_t)bg*S_*D_;

    float acc[2][4][4];
    #pragma unroll
    for (int i = 0; i < 2; i++)
        #pragma unroll
        for (int j = 0; j < 4; j++)
            #pragma unroll
            for (int q = 0; q < 4; q++) acc[i][j][q] = 0.f;

    {   // preload chunk 0
        char* st = sm;
        ld_chunk32(st,         pf, S_, 128);
        ld_chunk64(st + 10240, vf, D_, 32);
        CP_COMMIT();
    }
    for (int c = 0; c < 64; c++) {
        if (c < 63) {
            int k0 = (c+1)*32;
            char* st = sm + ((c+1)&1)*CTX_STAGE;
            ld_chunk32(st,         pf + k0, S_, 128);
            ld_chunk64(st + 10240, vf + (size_t)k0*D_, D_, 32);
            CP_COMMIT(); CP_WAIT1();
        } else CP_WAIT0();
        __syncthreads();
        const char* st = sm + (c&1)*CTX_STAGE;
        const char* vF = st + 10240;
        #pragma unroll
        for (int ks = 0; ks < 2; ks++) {
            int kb = ks*32 + tg*4;
            uint32_t aF[2][4], bF[4][2];
            #pragma unroll
            for (int i = 0; i < 2; i++) {
                int r0 = wm*32 + i*16 + g;
                lda4(aF[i], st, 80, r0, kb);
            }
            int krow = ks*16 + tg*2;
            #pragma unroll
            for (int j = 0; j < 4; j++) {
                int n2 = (wn*32 + j*8 + g)*2;
                uint32_t x0, x1, x2, x3;
                x0 = *(const unsigned short*)(vF + (krow  )*144 + n2);
                x1 = *(const unsigned short*)(vF + (krow+1)*144 + n2);
                x2 = *(const unsigned short*)(vF + (krow+8)*144 + n2);
                x3 = *(const unsigned short*)(vF + (krow+9)*144 + n2);
                bF[j][0] = x0 | (x1 << 16);
                bF[j][1] = x2 | (x3 << 16);
            }
            #pragma unroll
            for (int i = 0; i < 2; i++)
                #pragma unroll
                for (int j = 0; j < 4; j++)
                    mma_f16(acc[i][j], aF[i], bF[j]);
        }
        __syncthreads();
    }

    #pragma unroll
    for (int i = 0; i < 2; i++)
        #pragma unroll
        for (int j = 0; j < 4; j++) {
            int d = wn*32 + j*8 + tg*2;
            #pragma unroll
            for (int half = 0; half < 2; half++) {
                int q = bm + wm*32 + i*16 + g + half*8;
                float v0 = acc[i][j][half*2+0];
                float v1 = acc[i][j][half*2+1];
                __nv_bfloat16 h0,l0,h1,l1;
                split2(v0,h0,l0); split2(v1,h1,l1);
                size_t idx = ((size_t)b*S_ + q)*E_ + ghead*D_ + d;
                __nv_bfloat162 ph2; ph2.x=h0; ph2.y=h1;
                __nv_bfloat162 pl2; pl2.x=l0; pl2.y=l1;
                *(__nv_bfloat162*)&d_Ch[idx] = ph2;
                *(__nv_bfloat162*)&d_Cl[idx] = pl2;
            }
        }
}

// ===========================================================================
// kernel_launch
// ===========================================================================
extern "C" void kernel_launch(void* const* d_in, const int* in_sizes, int n_in,
                              void* d_out, int out_size)
{
    (void)in_sizes; (void)n_in; (void)out_size;
    const float* query = (const float*)d_in[0];
    const float* key_  = (const float*)d_in[1];
    const float* value = (const float*)d_in[2];
    const float* Wq = (const float*)d_in[3];
    const float* bq = (const float*)d_in[4];
    const float* Wk = (const float*)d_in[5];
    const float* bk = (const float*)d_in[6];
    const float* Wv = (const float*)d_in[7];
    const float* bv = (const float*)d_in[8];
    const float* hm = (const float*)d_in[9];
    const float* Wo = (const float*)d_in[10];
    const float* bo = (const float*)d_in[11];
    float* out = (float*)d_out;

    cudaFuncSetAttribute(gemm_qkv,           cudaFuncAttributeMaxDynamicSharedMemorySize, PROJ_SMEM);
    cudaFuncSetAttribute(gemm_out,           cudaFuncAttributeMaxDynamicSharedMemorySize, PROJ_SMEM);
    cudaFuncSetAttribute(scores_mma,         cudaFuncAttributeMaxDynamicSharedMemorySize, SC_SMEM);
    cudaFuncSetAttribute(softmax_mix_kernel, cudaFuncAttributeMaxDynamicSharedMemorySize, SMX_SMEM);
    cudaFuncSetAttribute(ctx_mma,            cudaFuncAttributeMaxDynamicSharedMemorySize, CTX_SMEM);

    const int n4 = TOK_*E_/4;

    mix_softmax_kernel<<<1, 16>>>(hm);
    split_wt3<<<dim3(32, 32, 3), dim3(32, 8)>>>(Wq, Wk, Wv);
    split_f3<<<dim3(n4/256, 1, 3), 256>>>(query, key_, value, n4);
    gemm_qkv<<<dim3(E_/128, TOK_/128, 3), 256, PROJ_SMEM>>>(bq, bk, bv);

    scores_mma<<<dim3(S_/128, S_/128, BH_), 256, SC_SMEM>>>();   // (16,16,32)
    softmax_mix_kernel<<<B_*S_, 256, SMX_SMEM>>>();              // 4096 blocks
    ctx_mma<<<dim3(S_/128, BH_), 256, CTX_SMEM>>>();             // (16,32)

    split_wt<<<dim3(32, 32), dim3(32, 8)>>>(Wo);
    gemm_out<<<dim3(E_/128, TOK_/128), 256, PROJ_SMEM>>>(bo, out);
}